// round 13
// baseline (speedup 1.0000x reference)
#include <cuda_runtime.h>
#include <cuda_bf16.h>
#include <cstdint>

// Problem constants (fixed by the reference)
#define NN 50000
#define EE 800000
#define FIN 256
#define HH 64
#define NGR 64
#define NCL 4

// ---------------- scratch (device globals; no allocs allowed) ----------------
__device__ int   g_edeg[NN];
__device__ float g_dinv[NN];
__device__ int   g_off[NN];
__device__ int   g_cursor[NN];
__device__ int   g_csrc[EE];
__device__ int   g_counter;
__device__ __align__(128) float g_h[(size_t)NN * HH];        // gemm out (fp32, self term)
__device__ __align__(128) __nv_bfloat162 g_hb[(size_t)NN * 32];  // bf16 mirror for gathers
__device__ __align__(128) float g_a[(size_t)NN * HH];
__device__ float g_pool[NGR * HH];
__device__ float g_cnt[NGR];

// ---------------- init ----------------
__global__ void k_init() {
    int t = blockIdx.x * blockDim.x + threadIdx.x;
    if (t < NN) g_edeg[t] = 0;
    if (t < NGR * HH) g_pool[t] = 0.0f;
    if (t < NGR) g_cnt[t] = 0.0f;
    if (t == 0) g_counter = 0;
}

// ---------------- degree ----------------
__global__ void k_deg(const int* __restrict__ ei) {
    int e = blockIdx.x * blockDim.x + threadIdx.x;
    if (e < EE) atomicAdd(&g_edeg[ei[EE + e]], 1);
}

// ---------------- chunk allocation + dinv (warp-aggregated atomic) ----------------
__global__ void k_alloc() {
    int i = blockIdx.x * blockDim.x + threadIdx.x;
    int lane = threadIdx.x & 31;
    int v = (i < NN) ? g_edeg[i] : 0;
    int s = v;
    #pragma unroll
    for (int o = 1; o < 32; o <<= 1) {
        int t = __shfl_up_sync(0xFFFFFFFFu, s, o);
        if (lane >= o) s += t;
    }
    int total = __shfl_sync(0xFFFFFFFFu, s, 31);
    int base = 0;
    if (lane == 31) base = atomicAdd(&g_counter, total);
    base = __shfl_sync(0xFFFFFFFFu, base, 31);
    if (i < NN) {
        int beg = base + s - v;
        g_off[i] = beg;
        g_cursor[i] = beg;
        g_dinv[i] = rsqrtf((float)(v + 1));
    }
}

// ---------------- scatter ----------------
__global__ void k_scatter(const int* __restrict__ ei) {
    int e = blockIdx.x * blockDim.x + threadIdx.x;
    if (e < EE) {
        int src = ei[e];
        int dst = ei[EE + e];
        int pos = atomicAdd(&g_cursor[dst], 1);
        g_csrc[pos] = src;
    }
}

// ---------------- packed f32x2 helpers ----------------
__device__ __forceinline__ unsigned long long splat2(float a) {
    unsigned long long r;
    asm("mov.b64 %0, {%1, %1};" : "=l"(r) : "f"(a));
    return r;
}
__device__ __forceinline__ void fma2(unsigned long long& acc, unsigned long long a,
                                     unsigned long long b) {
    asm("fma.rn.f32x2 %0, %1, %2, %0;" : "+l"(acc) : "l"(a), "l"(b));
}
__device__ __forceinline__ float2 unpack2(unsigned long long v) {
    float2 r;
    asm("mov.b64 {%0, %1}, %2;" : "=f"(r.x), "=f"(r.y) : "l"(v));
    return r;
}

// ---------------- tiled fp32 GEMM w/ packed FFMA2: C[M,64] = act(A[M,K]) @ W[K,64] ------
// Epilogue also writes bf16 mirror Cb for the gather kernel.
template <int K, bool RELU>
__device__ __forceinline__ void gemm_body(const float* __restrict__ A,
                                          const float* __restrict__ W,
                                          float* __restrict__ C,
                                          __nv_bfloat162* __restrict__ Cb, int M) {
    __shared__ float As[64][65];
    __shared__ __align__(16) float Ws[64][64];
    int tid = threadIdx.x;
    int tx = tid & 15, ty = tid >> 4;
    int row0 = blockIdx.x * 64;
    unsigned long long acc01[4] = {0ull, 0ull, 0ull, 0ull};
    unsigned long long acc23[4] = {0ull, 0ull, 0ull, 0ull};

    for (int k0 = 0; k0 < K; k0 += 64) {
        #pragma unroll
        for (int it = 0; it < 4; it++) {
            int l = tid + it * 256;
            int r = l >> 4, c4 = l & 15;
            int grow = row0 + r;
            float4 v = make_float4(0.f, 0.f, 0.f, 0.f);
            if (grow < M)
                v = *(const float4*)(A + (size_t)grow * K + k0 + c4 * 4);
            if (RELU) {
                v.x = fmaxf(v.x, 0.f); v.y = fmaxf(v.y, 0.f);
                v.z = fmaxf(v.z, 0.f); v.w = fmaxf(v.w, 0.f);
            }
            As[r][c4 * 4 + 0] = v.x; As[r][c4 * 4 + 1] = v.y;
            As[r][c4 * 4 + 2] = v.z; As[r][c4 * 4 + 3] = v.w;
        }
        #pragma unroll
        for (int it = 0; it < 4; it++) {
            int l = tid + it * 256;
            int r = l >> 4, c4 = l & 15;
            *(float4*)&Ws[r][c4 * 4] =
                *(const float4*)(W + (size_t)(k0 + r) * 64 + c4 * 4);
        }
        __syncthreads();
        #pragma unroll
        for (int kk = 0; kk < 64; kk++) {
            const double2 bb = *(const double2*)&Ws[kk][tx * 4];
            unsigned long long b01 = __double_as_longlong(bb.x);
            unsigned long long b23 = __double_as_longlong(bb.y);
            unsigned long long s0 = splat2(As[ty * 4 + 0][kk]);
            unsigned long long s1 = splat2(As[ty * 4 + 1][kk]);
            unsigned long long s2 = splat2(As[ty * 4 + 2][kk]);
            unsigned long long s3 = splat2(As[ty * 4 + 3][kk]);
            fma2(acc01[0], s0, b01); fma2(acc23[0], s0, b23);
            fma2(acc01[1], s1, b01); fma2(acc23[1], s1, b23);
            fma2(acc01[2], s2, b01); fma2(acc23[2], s2, b23);
            fma2(acc01[3], s3, b01); fma2(acc23[3], s3, b23);
        }
        __syncthreads();
    }
    #pragma unroll
    for (int i = 0; i < 4; i++) {
        int grow = row0 + ty * 4 + i;
        if (grow < M) {
            float2 p01 = unpack2(acc01[i]);
            float2 p23 = unpack2(acc23[i]);
            float4 v = make_float4(p01.x, p01.y, p23.x, p23.y);
            *(float4*)(C + (size_t)grow * 64 + tx * 4) = v;
            // bf16 mirror: 2 x bf162 = cols (4tx..4tx+3)
            __nv_bfloat162 b0 = __floats2bfloat162_rn(p01.x, p01.y);
            __nv_bfloat162 b1 = __floats2bfloat162_rn(p23.x, p23.y);
            *(uint2*)(Cb + (size_t)grow * 32 + tx * 2) =
                make_uint2(*(uint32_t*)&b0, *(uint32_t*)&b1);
        }
    }
}

__global__ void __launch_bounds__(256) k_gemm1(const float* __restrict__ A,
                                               const float* __restrict__ W) {
    gemm_body<FIN, false>(A, W, g_h, g_hb, NN);
}
__global__ void __launch_bounds__(256) k_gemm2(const float* __restrict__ W) {
    gemm_body<HH, true>(g_a, W, g_h, g_hb, NN);
}

// ---------------- aggregation: warp per dst node; bf16 neighbor gather ----------------
// g_a[i] = bias + dinv[i]^2 * h[i](fp32) + sum_e dinv[src]*dinv[i] * hb[src](bf16)
__global__ void k_agg(const float* __restrict__ bias) {
    int gt = blockIdx.x * blockDim.x + threadIdx.x;
    int i = gt >> 5;
    int lane = threadIdx.x & 31;
    if (i >= NN) return;
    int beg = g_off[i];
    int end = beg + g_edeg[i];
    float di = g_dinv[i];
    float2 hv = *(const float2*)(g_h + (size_t)i * HH + lane * 2);
    float s = di * di;
    float2 acc;
    acc.x = hv.x * s;
    acc.y = hv.y * s;
    for (int e = beg; e < end; e++) {
        int src = g_csrc[e];
        float norm = g_dinv[src] * di;
        float2 v = __bfloat1622float2(g_hb[(size_t)src * 32 + lane]);
        acc.x += v.x * norm;
        acc.y += v.y * norm;
    }
    const float2 b = *(const float2*)(bias + lane * 2);
    acc.x += b.x;
    acc.y += b.y;
    *(float2*)(g_a + (size_t)i * HH + lane * 2) = acc;
}

// ---------------- mean pool (relu fused); batch is SORTED ----------------
#define POOL_BLOCKS 256
__global__ void k_pool(const int* __restrict__ batch) {
    const int CH = (NN + POOL_BLOCKS - 1) / POOL_BLOCKS;
    int f = threadIdx.x;
    int beg = blockIdx.x * CH;
    int end = min(beg + CH, NN);
    if (beg >= end) return;
    float acc = 0.f, cnt = 0.f;
    int curg = batch[beg];
    for (int i = beg; i < end; i++) {
        int g = batch[i];
        if (g != curg) {
            atomicAdd(&g_pool[curg * HH + f], acc);
            if (f == 0) atomicAdd(&g_cnt[curg], cnt);
            acc = 0.f; cnt = 0.f; curg = g;
        }
        acc += fmaxf(g_a[(size_t)i * HH + f], 0.f);
        cnt += 1.f;
    }
    atomicAdd(&g_pool[curg * HH + f], acc);
    if (f == 0) atomicAdd(&g_cnt[curg], cnt);
}

// ---------------- fused MLP head: one block per graph ----------------
__global__ void k_head(const float* __restrict__ fc1w, const float* __restrict__ fc1b,
                       const float* __restrict__ fc2w, const float* __restrict__ fc2b,
                       float* __restrict__ out) {
    __shared__ float z[128];
    int g = blockIdx.x;
    int j = threadIdx.x;   // 0..127
    float inv = 1.0f / fmaxf(g_cnt[g], 1.0f);
    float s = fc1b[j];
    #pragma unroll 8
    for (int f = 0; f < HH; f++)
        s += (g_pool[g * HH + f] * inv) * fc1w[f * 128 + j];
    z[j] = fmaxf(s, 0.f);
    __syncthreads();
    if (j < NCL) {
        float o = fc2b[j];
        #pragma unroll 16
        for (int q = 0; q < 128; q++)
            o += z[q] * fc2w[q * NCL + j];
        out[g * NCL + j] = o;
    }
}

// ---------------- launch ----------------
extern "C" void kernel_launch(void* const* d_in, const int* in_sizes, int n_in,
                              void* d_out, int out_size) {
    const float* x    = (const float*)d_in[0];
    const int* ei     = (const int*)d_in[1];
    const int* bat    = (const int*)d_in[2];
    const float* W1   = (const float*)d_in[3];
    const float* b1   = (const float*)d_in[4];
    const float* W2   = (const float*)d_in[5];
    const float* b2   = (const float*)d_in[6];
    const float* fc1w = (const float*)d_in[7];
    const float* fc1b = (const float*)d_in[8];
    const float* fc2w = (const float*)d_in[9];
    const float* fc2b = (const float*)d_in[10];
    float* out        = (float*)d_out;

    static cudaStream_t s_pre = nullptr;
    static cudaEvent_t ev_root = nullptr, ev_pre = nullptr;
    if (!s_pre) {
        cudaStreamCreateWithFlags(&s_pre, cudaStreamNonBlocking);
        cudaEventCreateWithFlags(&ev_root, cudaEventDisableTiming);
        cudaEventCreateWithFlags(&ev_pre, cudaEventDisableTiming);
    }

    // fork: CSR build on side stream, overlapped with gemm1
    cudaEventRecord(ev_root, 0);
    cudaStreamWaitEvent(s_pre, ev_root, 0);
    k_init<<<(NN + 255) / 256, 256, 0, s_pre>>>();
    k_deg<<<(EE + 255) / 256, 256, 0, s_pre>>>(ei);
    k_alloc<<<(NN + 255) / 256, 256, 0, s_pre>>>();
    k_scatter<<<(EE + 255) / 256, 256, 0, s_pre>>>(ei);
    cudaEventRecord(ev_pre, s_pre);

    // main stream: gemm1 (independent of CSR build)
    k_gemm1<<<(NN + 63) / 64, 256>>>(x, W1);

    cudaStreamWaitEvent(0, ev_pre, 0);

    k_agg<<<(NN * 32 + 255) / 256, 256>>>(b1);
    k_gemm2<<<(NN + 63) / 64, 256>>>(W2);
    k_agg<<<(NN * 32 + 255) / 256, 256>>>(b2);

    k_pool<<<POOL_BLOCKS, HH>>>(bat);
    k_head<<<NGR, 128>>>(fc1w, fc1b, fc2w, fc2b, out);
}

// round 14
// speedup vs baseline: 1.0501x; 1.0501x over previous
#include <cuda_runtime.h>
#include <cstdint>

// Problem constants (fixed by the reference)
#define NN 50000
#define EE 800000
#define FIN 256
#define HH 64
#define NGR 64
#define NCL 4

// ---------------- scratch (device globals; no allocs allowed) ----------------
__device__ int   g_edeg[NN];
__device__ float g_dinv[NN];
__device__ int   g_off[NN];
__device__ int   g_cursor[NN];
__device__ int   g_csrc[EE];
__device__ int   g_counter;
__device__ __align__(128) float g_h[(size_t)NN * HH];
__device__ __align__(128) float g_a[(size_t)NN * HH];
__device__ float g_pool[NGR * HH];
__device__ float g_cnt[NGR];

// ---------------- init ----------------
__global__ void k_init() {
    int t = blockIdx.x * blockDim.x + threadIdx.x;
    if (t < NN) g_edeg[t] = 0;
    if (t < NGR * HH) g_pool[t] = 0.0f;
    if (t < NGR) g_cnt[t] = 0.0f;
    if (t == 0) g_counter = 0;
}

// ---------------- degree ----------------
__global__ void k_deg(const int* __restrict__ ei) {
    int e = blockIdx.x * blockDim.x + threadIdx.x;
    if (e < EE) atomicAdd(&g_edeg[ei[EE + e]], 1);
}

// ---------------- chunk allocation + dinv (warp-aggregated atomic) ----------------
__global__ void k_alloc() {
    int i = blockIdx.x * blockDim.x + threadIdx.x;
    int lane = threadIdx.x & 31;
    int v = (i < NN) ? g_edeg[i] : 0;
    int s = v;
    #pragma unroll
    for (int o = 1; o < 32; o <<= 1) {
        int t = __shfl_up_sync(0xFFFFFFFFu, s, o);
        if (lane >= o) s += t;
    }
    int total = __shfl_sync(0xFFFFFFFFu, s, 31);
    int base = 0;
    if (lane == 31) base = atomicAdd(&g_counter, total);
    base = __shfl_sync(0xFFFFFFFFu, base, 31);
    if (i < NN) {
        int beg = base + s - v;
        g_off[i] = beg;
        g_cursor[i] = beg;
        g_dinv[i] = rsqrtf((float)(v + 1));
    }
}

// ---------------- scatter ----------------
__global__ void k_scatter(const int* __restrict__ ei) {
    int e = blockIdx.x * blockDim.x + threadIdx.x;
    if (e < EE) {
        int src = ei[e];
        int dst = ei[EE + e];
        int pos = atomicAdd(&g_cursor[dst], 1);
        g_csrc[pos] = src;
    }
}

// ---------------- packed f32x2 helpers ----------------
__device__ __forceinline__ unsigned long long splat2(float a) {
    unsigned long long r;
    asm("mov.b64 %0, {%1, %1};" : "=l"(r) : "f"(a));
    return r;
}
__device__ __forceinline__ void fma2(unsigned long long& acc, unsigned long long a,
                                     unsigned long long b) {
    asm("fma.rn.f32x2 %0, %1, %2, %0;" : "+l"(acc) : "l"(a), "l"(b));
}
__device__ __forceinline__ float2 unpack2(unsigned long long v) {
    float2 r;
    asm("mov.b64 {%0, %1}, %2;" : "=f"(r.x), "=f"(r.y) : "l"(v));
    return r;
}

// ---------------- tiled fp32 GEMM w/ packed FFMA2: C[M,64] = act(A[M,K]) @ W[K,64] ------
template <int K, bool RELU>
__device__ __forceinline__ void gemm_body(const float* __restrict__ A,
                                          const float* __restrict__ W,
                                          float* __restrict__ C, int M) {
    __shared__ float As[64][65];
    __shared__ __align__(16) float Ws[64][64];
    int tid = threadIdx.x;
    int tx = tid & 15, ty = tid >> 4;
    int row0 = blockIdx.x * 64;
    unsigned long long acc01[4] = {0ull, 0ull, 0ull, 0ull};
    unsigned long long acc23[4] = {0ull, 0ull, 0ull, 0ull};

    for (int k0 = 0; k0 < K; k0 += 64) {
        #pragma unroll
        for (int it = 0; it < 4; it++) {
            int l = tid + it * 256;
            int r = l >> 4, c4 = l & 15;
            int grow = row0 + r;
            float4 v = make_float4(0.f, 0.f, 0.f, 0.f);
            if (grow < M)
                v = *(const float4*)(A + (size_t)grow * K + k0 + c4 * 4);
            if (RELU) {
                v.x = fmaxf(v.x, 0.f); v.y = fmaxf(v.y, 0.f);
                v.z = fmaxf(v.z, 0.f); v.w = fmaxf(v.w, 0.f);
            }
            As[r][c4 * 4 + 0] = v.x; As[r][c4 * 4 + 1] = v.y;
            As[r][c4 * 4 + 2] = v.z; As[r][c4 * 4 + 3] = v.w;
        }
        #pragma unroll
        for (int it = 0; it < 4; it++) {
            int l = tid + it * 256;
            int r = l >> 4, c4 = l & 15;
            *(float4*)&Ws[r][c4 * 4] =
                *(const float4*)(W + (size_t)(k0 + r) * 64 + c4 * 4);
        }
        __syncthreads();
        #pragma unroll
        for (int kk = 0; kk < 64; kk++) {
            const double2 bb = *(const double2*)&Ws[kk][tx * 4];
            unsigned long long b01 = __double_as_longlong(bb.x);
            unsigned long long b23 = __double_as_longlong(bb.y);
            unsigned long long s0 = splat2(As[ty * 4 + 0][kk]);
            unsigned long long s1 = splat2(As[ty * 4 + 1][kk]);
            unsigned long long s2 = splat2(As[ty * 4 + 2][kk]);
            unsigned long long s3 = splat2(As[ty * 4 + 3][kk]);
            fma2(acc01[0], s0, b01); fma2(acc23[0], s0, b23);
            fma2(acc01[1], s1, b01); fma2(acc23[1], s1, b23);
            fma2(acc01[2], s2, b01); fma2(acc23[2], s2, b23);
            fma2(acc01[3], s3, b01); fma2(acc23[3], s3, b23);
        }
        __syncthreads();
    }
    #pragma unroll
    for (int i = 0; i < 4; i++) {
        int grow = row0 + ty * 4 + i;
        if (grow < M) {
            float2 p01 = unpack2(acc01[i]);
            float2 p23 = unpack2(acc23[i]);
            float4 v = make_float4(p01.x, p01.y, p23.x, p23.y);
            *(float4*)(C + (size_t)grow * 64 + tx * 4) = v;
        }
    }
}

__global__ void __launch_bounds__(256) k_gemm1(const float* __restrict__ A,
                                               const float* __restrict__ W) {
    gemm_body<FIN, false>(A, W, g_h, NN);
}
__global__ void __launch_bounds__(256) k_gemm2(const float* __restrict__ W) {
    gemm_body<HH, true>(g_a, W, g_h, NN);
}

// ---------------- aggregation: warp per dst node, 4x unrolled gather (MLP=4) ----------
__global__ void k_agg(const float* __restrict__ bias) {
    int gt = blockIdx.x * blockDim.x + threadIdx.x;
    int i = gt >> 5;
    int lane = threadIdx.x & 31;
    if (i >= NN) return;
    int beg = g_off[i];
    int deg = g_edeg[i];
    int end = beg + deg;
    float di = g_dinv[i];
    float2 hv = *(const float2*)(g_h + (size_t)i * HH + lane * 2);
    float s = di * di;
    float2 a0, a1, a2, a3;
    a0.x = hv.x * s; a0.y = hv.y * s;
    a1.x = 0.f; a1.y = 0.f;
    a2.x = 0.f; a2.y = 0.f;
    a3.x = 0.f; a3.y = 0.f;

    int e = beg;
    for (; e + 4 <= end; e += 4) {
        // batch index loads (independent)
        int s0 = g_csrc[e + 0];
        int s1 = g_csrc[e + 1];
        int s2 = g_csrc[e + 2];
        int s3 = g_csrc[e + 3];
        // batch norm loads
        float n0 = g_dinv[s0];
        float n1 = g_dinv[s1];
        float n2 = g_dinv[s2];
        float n3 = g_dinv[s3];
        // batch gathers (independent -> MLP=4)
        float2 v0 = *(const float2*)(g_h + (size_t)s0 * HH + lane * 2);
        float2 v1 = *(const float2*)(g_h + (size_t)s1 * HH + lane * 2);
        float2 v2 = *(const float2*)(g_h + (size_t)s2 * HH + lane * 2);
        float2 v3 = *(const float2*)(g_h + (size_t)s3 * HH + lane * 2);
        n0 *= di; n1 *= di; n2 *= di; n3 *= di;
        a0.x += v0.x * n0; a0.y += v0.y * n0;
        a1.x += v1.x * n1; a1.y += v1.y * n1;
        a2.x += v2.x * n2; a2.y += v2.y * n2;
        a3.x += v3.x * n3; a3.y += v3.y * n3;
    }
    for (; e < end; e++) {
        int src = g_csrc[e];
        float norm = g_dinv[src] * di;
        float2 v = *(const float2*)(g_h + (size_t)src * HH + lane * 2);
        a0.x += v.x * norm; a0.y += v.y * norm;
    }
    const float2 b = *(const float2*)(bias + lane * 2);
    float2 acc;
    acc.x = (a0.x + a1.x) + (a2.x + a3.x) + b.x;
    acc.y = (a0.y + a1.y) + (a2.y + a3.y) + b.y;
    *(float2*)(g_a + (size_t)i * HH + lane * 2) = acc;
}

// ---------------- mean pool (relu fused); batch is SORTED ----------------
#define POOL_BLOCKS 256
__global__ void k_pool(const int* __restrict__ batch) {
    const int CH = (NN + POOL_BLOCKS - 1) / POOL_BLOCKS;
    int f = threadIdx.x;
    int beg = blockIdx.x * CH;
    int end = min(beg + CH, NN);
    if (beg >= end) return;
    float acc = 0.f, cnt = 0.f;
    int curg = batch[beg];
    for (int i = beg; i < end; i++) {
        int g = batch[i];
        if (g != curg) {
            atomicAdd(&g_pool[curg * HH + f], acc);
            if (f == 0) atomicAdd(&g_cnt[curg], cnt);
            acc = 0.f; cnt = 0.f; curg = g;
        }
        acc += fmaxf(g_a[(size_t)i * HH + f], 0.f);
        cnt += 1.f;
    }
    atomicAdd(&g_pool[curg * HH + f], acc);
    if (f == 0) atomicAdd(&g_cnt[curg], cnt);
}

// ---------------- fused MLP head: one block per graph ----------------
__global__ void k_head(const float* __restrict__ fc1w, const float* __restrict__ fc1b,
                       const float* __restrict__ fc2w, const float* __restrict__ fc2b,
                       float* __restrict__ out) {
    __shared__ float z[128];
    int g = blockIdx.x;
    int j = threadIdx.x;   // 0..127
    float inv = 1.0f / fmaxf(g_cnt[g], 1.0f);
    float s = fc1b[j];
    #pragma unroll 8
    for (int f = 0; f < HH; f++)
        s += (g_pool[g * HH + f] * inv) * fc1w[f * 128 + j];
    z[j] = fmaxf(s, 0.f);
    __syncthreads();
    if (j < NCL) {
        float o = fc2b[j];
        #pragma unroll 16
        for (int q = 0; q < 128; q++)
            o += z[q] * fc2w[q * NCL + j];
        out[g * NCL + j] = o;
    }
}

// ---------------- launch ----------------
extern "C" void kernel_launch(void* const* d_in, const int* in_sizes, int n_in,
                              void* d_out, int out_size) {
    const float* x    = (const float*)d_in[0];
    const int* ei     = (const int*)d_in[1];
    const int* bat    = (const int*)d_in[2];
    const float* W1   = (const float*)d_in[3];
    const float* b1   = (const float*)d_in[4];
    const float* W2   = (const float*)d_in[5];
    const float* b2   = (const float*)d_in[6];
    const float* fc1w = (const float*)d_in[7];
    const float* fc1b = (const float*)d_in[8];
    const float* fc2w = (const float*)d_in[9];
    const float* fc2b = (const float*)d_in[10];
    float* out        = (float*)d_out;

    static cudaStream_t s_pre = nullptr;
    static cudaEvent_t ev_root = nullptr, ev_pre = nullptr;
    if (!s_pre) {
        cudaStreamCreateWithFlags(&s_pre, cudaStreamNonBlocking);
        cudaEventCreateWithFlags(&ev_root, cudaEventDisableTiming);
        cudaEventCreateWithFlags(&ev_pre, cudaEventDisableTiming);
    }

    // fork: CSR build on side stream, overlapped with gemm1
    cudaEventRecord(ev_root, 0);
    cudaStreamWaitEvent(s_pre, ev_root, 0);
    k_init<<<(NN + 255) / 256, 256, 0, s_pre>>>();
    k_deg<<<(EE + 255) / 256, 256, 0, s_pre>>>(ei);
    k_alloc<<<(NN + 255) / 256, 256, 0, s_pre>>>();
    k_scatter<<<(EE + 255) / 256, 256, 0, s_pre>>>(ei);
    cudaEventRecord(ev_pre, s_pre);

    // main stream: gemm1 (independent of CSR build)
    k_gemm1<<<(NN + 63) / 64, 256>>>(x, W1);

    cudaStreamWaitEvent(0, ev_pre, 0);

    k_agg<<<(NN * 32 + 255) / 256, 256>>>(b1);
    k_gemm2<<<(NN + 63) / 64, 256>>>(W2);
    k_agg<<<(NN * 32 + 255) / 256, 256>>>(b2);

    k_pool<<<POOL_BLOCKS, HH>>>(bat);
    k_head<<<NGR, 128>>>(fc1w, fc1b, fc2w, fc2b, out);
}

// round 15
// speedup vs baseline: 1.4962x; 1.4248x over previous
#include <cuda_runtime.h>
#include <cstdint>

// Problem constants (fixed by the reference)
#define NN 50000
#define EE 800000
#define FIN 256
#define HH 64
#define NGR 64
#define NCL 4

// ---------------- scratch (device globals; no allocs allowed) ----------------
// Self-cleaning invariant: every global this pipeline mutates is returned to
// its pre-run state (zeros where required) by the end of each run.
__device__ int   g_edeg[NN];        // zeroed-on-read in k_alloc
__device__ float g_dinv[NN];
__device__ int2  g_span[NN];        // (beg, deg) per node
__device__ int   g_cursor[NN];
__device__ int   g_csrc[EE];
__device__ int   g_counter;         // reset at start of k_deg
__device__ __align__(128) float g_h[(size_t)NN * HH];
__device__ __align__(128) float g_a[(size_t)NN * HH];
__device__ float g_pool[NGR * HH];  // zeroed-on-consume in k_head
__device__ float g_cnt[NGR];        // zeroed-on-consume in k_head

// ---------------- degree (+ counter reset) ----------------
__global__ void k_deg(const int* __restrict__ ei) {
    int e = blockIdx.x * blockDim.x + threadIdx.x;
    if (e == 0) g_counter = 0;   // consumed only by k_alloc (runs strictly after)
    if (e < EE) atomicAdd(&g_edeg[ei[EE + e]], 1);
}

// ---------------- chunk allocation + dinv (warp-aggregated atomic) ----------------
__global__ void k_alloc() {
    int i = blockIdx.x * blockDim.x + threadIdx.x;
    int lane = threadIdx.x & 31;
    int v = (i < NN) ? g_edeg[i] : 0;
    int s = v;
    #pragma unroll
    for (int o = 1; o < 32; o <<= 1) {
        int t = __shfl_up_sync(0xFFFFFFFFu, s, o);
        if (lane >= o) s += t;
    }
    int total = __shfl_sync(0xFFFFFFFFu, s, 31);
    int base = 0;
    if (lane == 31) base = atomicAdd(&g_counter, total);
    base = __shfl_sync(0xFFFFFFFFu, base, 31);
    if (i < NN) {
        int beg = base + s - v;
        g_span[i] = make_int2(beg, v);
        g_cursor[i] = beg;
        g_dinv[i] = rsqrtf((float)(v + 1));
        g_edeg[i] = 0;            // self-clean for next run's k_deg
    }
}

// ---------------- scatter ----------------
__global__ void k_scatter(const int* __restrict__ ei) {
    int e = blockIdx.x * blockDim.x + threadIdx.x;
    if (e < EE) {
        int src = ei[e];
        int dst = ei[EE + e];
        int pos = atomicAdd(&g_cursor[dst], 1);
        g_csrc[pos] = src;
    }
}

// ---------------- packed f32x2 helpers ----------------
__device__ __forceinline__ unsigned long long splat2(float a) {
    unsigned long long r;
    asm("mov.b64 %0, {%1, %1};" : "=l"(r) : "f"(a));
    return r;
}
__device__ __forceinline__ void fma2(unsigned long long& acc, unsigned long long a,
                                     unsigned long long b) {
    asm("fma.rn.f32x2 %0, %1, %2, %0;" : "+l"(acc) : "l"(a), "l"(b));
}
__device__ __forceinline__ float2 unpack2(unsigned long long v) {
    float2 r;
    asm("mov.b64 {%0, %1}, %2;" : "=f"(r.x), "=f"(r.y) : "l"(v));
    return r;
}

// ---------------- tiled fp32 GEMM w/ packed FFMA2: C[M,64] = act(A[M,K]) @ W[K,64] ------
template <int K, bool RELU>
__device__ __forceinline__ void gemm_body(const float* __restrict__ A,
                                          const float* __restrict__ W,
                                          float* __restrict__ C, int M) {
    __shared__ float As[64][65];
    __shared__ __align__(16) float Ws[64][64];
    int tid = threadIdx.x;
    int tx = tid & 15, ty = tid >> 4;
    int row0 = blockIdx.x * 64;
    unsigned long long acc01[4] = {0ull, 0ull, 0ull, 0ull};
    unsigned long long acc23[4] = {0ull, 0ull, 0ull, 0ull};

    for (int k0 = 0; k0 < K; k0 += 64) {
        #pragma unroll
        for (int it = 0; it < 4; it++) {
            int l = tid + it * 256;
            int r = l >> 4, c4 = l & 15;
            int grow = row0 + r;
            float4 v = make_float4(0.f, 0.f, 0.f, 0.f);
            if (grow < M)
                v = *(const float4*)(A + (size_t)grow * K + k0 + c4 * 4);
            if (RELU) {
                v.x = fmaxf(v.x, 0.f); v.y = fmaxf(v.y, 0.f);
                v.z = fmaxf(v.z, 0.f); v.w = fmaxf(v.w, 0.f);
            }
            As[r][c4 * 4 + 0] = v.x; As[r][c4 * 4 + 1] = v.y;
            As[r][c4 * 4 + 2] = v.z; As[r][c4 * 4 + 3] = v.w;
        }
        #pragma unroll
        for (int it = 0; it < 4; it++) {
            int l = tid + it * 256;
            int r = l >> 4, c4 = l & 15;
            *(float4*)&Ws[r][c4 * 4] =
                *(const float4*)(W + (size_t)(k0 + r) * 64 + c4 * 4);
        }
        __syncthreads();
        #pragma unroll
        for (int kk = 0; kk < 64; kk++) {
            const double2 bb = *(const double2*)&Ws[kk][tx * 4];
            unsigned long long b01 = __double_as_longlong(bb.x);
            unsigned long long b23 = __double_as_longlong(bb.y);
            unsigned long long s0 = splat2(As[ty * 4 + 0][kk]);
            unsigned long long s1 = splat2(As[ty * 4 + 1][kk]);
            unsigned long long s2 = splat2(As[ty * 4 + 2][kk]);
            unsigned long long s3 = splat2(As[ty * 4 + 3][kk]);
            fma2(acc01[0], s0, b01); fma2(acc23[0], s0, b23);
            fma2(acc01[1], s1, b01); fma2(acc23[1], s1, b23);
            fma2(acc01[2], s2, b01); fma2(acc23[2], s2, b23);
            fma2(acc01[3], s3, b01); fma2(acc23[3], s3, b23);
        }
        __syncthreads();
    }
    #pragma unroll
    for (int i = 0; i < 4; i++) {
        int grow = row0 + ty * 4 + i;
        if (grow < M) {
            float2 p01 = unpack2(acc01[i]);
            float2 p23 = unpack2(acc23[i]);
            float4 v = make_float4(p01.x, p01.y, p23.x, p23.y);
            *(float4*)(C + (size_t)grow * 64 + tx * 4) = v;
        }
    }
}

__global__ void __launch_bounds__(256) k_gemm1(const float* __restrict__ A,
                                               const float* __restrict__ W) {
    gemm_body<FIN, false>(A, W, g_h, NN);
}
__global__ void __launch_bounds__(256) k_gemm2(const float* __restrict__ W) {
    gemm_body<HH, true>(g_a, W, g_h, NN);
}

// ---------------- aggregation: warp per dst node ----------------
__global__ void k_agg(const float* __restrict__ bias) {
    int gt = blockIdx.x * blockDim.x + threadIdx.x;
    int i = gt >> 5;
    int lane = threadIdx.x & 31;
    if (i >= NN) return;
    int2 span = g_span[i];
    int beg = span.x;
    int end = beg + span.y;
    float di = g_dinv[i];
    float2 hv = *(const float2*)(g_h + (size_t)i * HH + lane * 2);
    float s = di * di;
    float2 acc;
    acc.x = hv.x * s;
    acc.y = hv.y * s;
    for (int e = beg; e < end; e++) {
        int src = g_csrc[e];
        float norm = g_dinv[src] * di;
        float2 v = *(const float2*)(g_h + (size_t)src * HH + lane * 2);
        acc.x += v.x * norm;
        acc.y += v.y * norm;
    }
    const float2 b = *(const float2*)(bias + lane * 2);
    acc.x += b.x;
    acc.y += b.y;
    *(float2*)(g_a + (size_t)i * HH + lane * 2) = acc;
}

// ---------------- mean pool (relu fused); batch is SORTED ----------------
// 3125 blocks x 16-node chunks (50000 = 3125*16): short chains, batched loads.
#define POOL_BLOCKS 3125
#define PCH 16
__global__ void k_pool(const int* __restrict__ batch) {
    int f = threadIdx.x;   // 0..63
    int beg = blockIdx.x * PCH;
    float v[PCH];
    int gg[PCH];
    // batch-prefetch: independent loads, high MLP
    #pragma unroll
    for (int q = 0; q < PCH; q++)
        v[q] = g_a[(size_t)(beg + q) * HH + f];
    #pragma unroll
    for (int q = 0; q < PCH; q++)
        gg[q] = batch[beg + q];
    float acc = 0.f, cnt = 0.f;
    int curg = gg[0];
    #pragma unroll
    for (int q = 0; q < PCH; q++) {
        if (gg[q] != curg) {
            atomicAdd(&g_pool[curg * HH + f], acc);
            if (f == 0) atomicAdd(&g_cnt[curg], cnt);
            acc = 0.f; cnt = 0.f; curg = gg[q];
        }
        acc += fmaxf(v[q], 0.f);
        cnt += 1.f;
    }
    atomicAdd(&g_pool[curg * HH + f], acc);
    if (f == 0) atomicAdd(&g_cnt[curg], cnt);
}

// ---------------- fused MLP head: one block per graph (+ pool self-clean) ----------------
__global__ void k_head(const float* __restrict__ fc1w, const float* __restrict__ fc1b,
                       const float* __restrict__ fc2w, const float* __restrict__ fc2b,
                       float* __restrict__ out) {
    __shared__ float z[128];
    int g = blockIdx.x;
    int j = threadIdx.x;   // 0..127
    float inv = 1.0f / fmaxf(g_cnt[g], 1.0f);
    float s = fc1b[j];
    #pragma unroll 8
    for (int f = 0; f < HH; f++)
        s += (g_pool[g * HH + f] * inv) * fc1w[f * 128 + j];
    z[j] = fmaxf(s, 0.f);
    __syncthreads();          // all g_pool/g_cnt reads complete past this point
    if (j < HH) g_pool[g * HH + j] = 0.0f;   // self-clean for next run
    if (j == HH) g_cnt[g] = 0.0f;
    if (j < NCL) {
        float o = fc2b[j];
        #pragma unroll 16
        for (int q = 0; q < 128; q++)
            o += z[q] * fc2w[q * NCL + j];
        out[g * NCL + j] = o;
    }
}

// ---------------- launch ----------------
extern "C" void kernel_launch(void* const* d_in, const int* in_sizes, int n_in,
                              void* d_out, int out_size) {
    const float* x    = (const float*)d_in[0];
    const int* ei     = (const int*)d_in[1];
    const int* bat    = (const int*)d_in[2];
    const float* W1   = (const float*)d_in[3];
    const float* b1   = (const float*)d_in[4];
    const float* W2   = (const float*)d_in[5];
    const float* b2   = (const float*)d_in[6];
    const float* fc1w = (const float*)d_in[7];
    const float* fc1b = (const float*)d_in[8];
    const float* fc2w = (const float*)d_in[9];
    const float* fc2b = (const float*)d_in[10];
    float* out        = (float*)d_out;

    static cudaStream_t s_pre = nullptr;
    static cudaEvent_t ev_root = nullptr, ev_pre = nullptr;
    if (!s_pre) {
        cudaStreamCreateWithFlags(&s_pre, cudaStreamNonBlocking);
        cudaEventCreateWithFlags(&ev_root, cudaEventDisableTiming);
        cudaEventCreateWithFlags(&ev_pre, cudaEventDisableTiming);
    }

    // fork: CSR build on side stream, overlapped with gemm1
    cudaEventRecord(ev_root, 0);
    cudaStreamWaitEvent(s_pre, ev_root, 0);
    k_deg<<<(EE + 255) / 256, 256, 0, s_pre>>>(ei);
    k_alloc<<<(NN + 255) / 256, 256, 0, s_pre>>>();
    k_scatter<<<(EE + 255) / 256, 256, 0, s_pre>>>(ei);
    cudaEventRecord(ev_pre, s_pre);

    // main stream: gemm1 (independent of CSR build)
    k_gemm1<<<(NN + 63) / 64, 256>>>(x, W1);

    cudaStreamWaitEvent(0, ev_pre, 0);

    k_agg<<<(NN * 32 + 255) / 256, 256>>>(b1);
    k_gemm2<<<(NN + 63) / 64, 256>>>(W2);
    k_agg<<<(NN * 32 + 255) / 256, 256>>>(b2);

    k_pool<<<POOL_BLOCKS, HH>>>(bat);
    k_head<<<NGR, 128>>>(fc1w, fc1b, fc2w, fc2b, out);
}